// round 2
// baseline (speedup 1.0000x reference)
#include <cuda_runtime.h>

#define Nn   20000
#define Ee   320000
#define XDIM 128
#define Hh   256
#define LL   4
#define GG   128
#define CC   10
#define EPSF 1e-5f

// ---------------- scratch (static device allocations) ----------------
__device__ float g_h [Nn * Hh];
__device__ float g_t [Nn * Hh];
__device__ float g_t2[Nn * Hh];
__device__ float g_dinv[Nn];
__device__ int   g_deg[Nn];
__device__ int   g_rowptr[Nn + 1];
__device__ int   g_cursor[Nn];
__device__ int   g_csrc[Ee];
__device__ float g_cw[Ee];
__device__ float g_colsum[Hh];
__device__ float g_colsq[Hh];
__device__ float g_scale[Hh];
__device__ float g_shift[Hh];
__device__ float g_gsum[GG * Hh];
__device__ int   g_gcnt[GG];
__device__ float g_m1[GG * Hh];
__device__ float g_m2[GG * Hh];

// ---------------- setup kernels ----------------
__global__ void zero_k() {
    int i = blockIdx.x * blockDim.x + threadIdx.x;
    if (i < Nn)      g_deg[i]  = 0;
    if (i < GG * Hh) g_gsum[i] = 0.f;
    if (i < GG)      g_gcnt[i] = 0;
}

__global__ void degree_k(const int* __restrict__ dst, const int* __restrict__ batch) {
    int i = blockIdx.x * blockDim.x + threadIdx.x;
    if (i < Ee) atomicAdd(&g_deg[dst[i]], 1);
    if (i < Nn) atomicAdd(&g_gcnt[batch[i]], 1);
}

__global__ void dinv_k() {
    int i = blockIdx.x * blockDim.x + threadIdx.x;
    if (i < Nn) g_dinv[i] = rsqrtf((float)g_deg[i] + 1.0f);
}

// single-block exclusive scan of g_deg -> g_rowptr (and g_cursor copy)
__global__ void scan_k() {
    __shared__ int ss[1024];
    const int CH = 20;
    int tid  = threadIdx.x;
    int base = tid * CH;
    int loc[CH];
    int s = 0;
#pragma unroll
    for (int c = 0; c < CH; c++) {
        int idx = base + c;
        int v   = (idx < Nn) ? g_deg[idx] : 0;
        loc[c]  = s;
        s += v;
    }
    ss[tid] = s;
    __syncthreads();
    if (tid == 0) {
        int run = 0;
        for (int i = 0; i < 1024; i++) { int t = ss[i]; ss[i] = run; run += t; }
    }
    __syncthreads();
    int off = ss[tid];
#pragma unroll
    for (int c = 0; c < CH; c++) {
        int idx = base + c;
        if (idx <= Nn) {
            int p = off + loc[c];
            g_rowptr[idx] = p;
            if (idx < Nn) g_cursor[idx] = p;
        }
    }
}

__global__ void place_k(const int* __restrict__ src, const int* __restrict__ dst) {
    int i = blockIdx.x * blockDim.x + threadIdx.x;
    if (i >= Ee) return;
    int s = src[i], d = dst[i];
    int pos = atomicAdd(&g_cursor[d], 1);
    g_csrc[pos] = s;
    g_cw[pos]   = g_dinv[s] * g_dinv[d];
}

// ---------------- GEMM body: C[M,256] = A[M,K] @ B[K,256] (+bias) ----------------
__device__ __forceinline__ void gemm_body(
    const float* __restrict__ A, const float* __restrict__ B,
    const float* __restrict__ bias, float* __restrict__ C, int M, int K)
{
    __shared__ float As[16][68];
    __shared__ float Bs[16][68];
    const int tid = threadIdx.x;
    const int tx = tid & 15, ty = tid >> 4;
    const int rowBase = blockIdx.y * 64;
    const int colBase = blockIdx.x * 64;
    const int am  = tid >> 2;
    const int akq = (tid & 3) * 4;
    const int bk  = tid >> 4;
    const int bn  = (tid & 15) * 4;

    float acc[4][4];
#pragma unroll
    for (int i = 0; i < 4; i++)
#pragma unroll
        for (int j = 0; j < 4; j++) acc[i][j] = 0.f;

    for (int k0 = 0; k0 < K; k0 += 16) {
        float4 av = make_float4(0.f, 0.f, 0.f, 0.f);
        int ar = rowBase + am;
        if (ar < M) av = *(const float4*)(A + (size_t)ar * K + k0 + akq);
        As[akq    ][am] = av.x;
        As[akq + 1][am] = av.y;
        As[akq + 2][am] = av.z;
        As[akq + 3][am] = av.w;
        *(float4*)&Bs[bk][bn] = *(const float4*)(B + (size_t)(k0 + bk) * Hh + colBase + bn);
        __syncthreads();
#pragma unroll
        for (int kk = 0; kk < 16; kk++) {
            float4 a = *(float4*)&As[kk][ty * 4];
            float4 b = *(float4*)&Bs[kk][tx * 4];
            acc[0][0] += a.x * b.x; acc[0][1] += a.x * b.y; acc[0][2] += a.x * b.z; acc[0][3] += a.x * b.w;
            acc[1][0] += a.y * b.x; acc[1][1] += a.y * b.y; acc[1][2] += a.y * b.z; acc[1][3] += a.y * b.w;
            acc[2][0] += a.z * b.x; acc[2][1] += a.z * b.y; acc[2][2] += a.z * b.z; acc[2][3] += a.z * b.w;
            acc[3][0] += a.w * b.x; acc[3][1] += a.w * b.y; acc[3][2] += a.w * b.z; acc[3][3] += a.w * b.w;
        }
        __syncthreads();
    }
#pragma unroll
    for (int i = 0; i < 4; i++) {
        int r = rowBase + ty * 4 + i;
        if (r < M) {
            int cb = colBase + tx * 4;
            float4 v;
            v.x = acc[i][0]; v.y = acc[i][1]; v.z = acc[i][2]; v.w = acc[i][3];
            if (bias) { v.x += bias[cb]; v.y += bias[cb + 1]; v.z += bias[cb + 2]; v.w += bias[cb + 3]; }
            *(float4*)(C + (size_t)r * Hh + cb) = v;
        }
    }
}

// encoder GEMM: x @ encW + encB -> g_h   (A = harness input, scratch resolved in device code)
__global__ __launch_bounds__(256) void gemm_enc_k(
    const float* __restrict__ x, const float* __restrict__ encW, const float* __restrict__ encB)
{
    gemm_body(x, encW, encB, g_h, Nn, XDIM);
}

// conv GEMM: g_h @ W -> g_t (no bias)
__global__ __launch_bounds__(256) void gemm_conv_k(const float* __restrict__ W)
{
    gemm_body(g_h, W, nullptr, g_t, Nn, Hh);
}

// ---------------- aggregate (warp per node, CSR gather) + self loop + bias ----------------
__global__ __launch_bounds__(256) void agg_k(const float* __restrict__ convBi) {
    int gtid = blockIdx.x * blockDim.x + threadIdx.x;
    if (gtid < Hh) { g_colsum[gtid] = 0.f; g_colsq[gtid] = 0.f; }  // zero stats for this layer
    int w = gtid >> 5, lane = gtid & 31;
    if (w >= Nn) return;
    int beg = g_rowptr[w], end = g_rowptr[w + 1];
    float4 a0 = make_float4(0.f, 0.f, 0.f, 0.f), a1 = a0;
    const float4* T = (const float4*)g_t;
    for (int e = beg; e < end; e++) {
        int   s  = g_csrc[e];
        float wt = g_cw[e];
        float4 v0 = T[s * 64 + lane];
        float4 v1 = T[s * 64 + lane + 32];
        a0.x += v0.x * wt; a0.y += v0.y * wt; a0.z += v0.z * wt; a0.w += v0.w * wt;
        a1.x += v1.x * wt; a1.y += v1.y * wt; a1.z += v1.z * wt; a1.w += v1.w * wt;
    }
    float sn = g_dinv[w]; sn *= sn;
    float4 t0 = T[w * 64 + lane], t1 = T[w * 64 + lane + 32];
    const float4* B4 = (const float4*)convBi;
    float4 b0 = B4[lane], b1 = B4[lane + 32];
    a0.x += t0.x * sn + b0.x; a0.y += t0.y * sn + b0.y;
    a0.z += t0.z * sn + b0.z; a0.w += t0.w * sn + b0.w;
    a1.x += t1.x * sn + b1.x; a1.y += t1.y * sn + b1.y;
    a1.z += t1.z * sn + b1.z; a1.w += t1.w * sn + b1.w;
    ((float4*)g_t2)[w * 64 + lane]      = a0;
    ((float4*)g_t2)[w * 64 + lane + 32] = a1;
}

// ---------------- column stats over g_t2 ----------------
__global__ void stats_k() {
    int j  = threadIdx.x;
    int r0 = blockIdx.x * 80;
    float s = 0.f, q = 0.f;
    for (int r = 0; r < 80; r++) {
        int n = r0 + r;
        if (n >= Nn) break;
        float v = g_t2[(size_t)n * Hh + j];
        s += v; q += v * v;
    }
    atomicAdd(&g_colsum[j], s);
    atomicAdd(&g_colsq[j], q);
}

__global__ void bnprep_k(const float* __restrict__ gamma, const float* __restrict__ beta, float invN) {
    int j = threadIdx.x;
    float m  = g_colsum[j] * invN;
    float v  = g_colsq[j] * invN - m * m;
    float rs = rsqrtf(v + EPSF);
    float sc = gamma[j] * rs;
    g_scale[j] = sc;
    g_shift[j] = beta[j] - m * sc;
}

__global__ void bnrelu_k() {
    int idx = blockIdx.x * blockDim.x + threadIdx.x;
    if (idx >= Nn * Hh / 4) return;
    int j = (idx & (Hh / 4 - 1)) * 4;
    float4 v = ((const float4*)g_t2)[idx];
    float4 o;
    o.x = fmaxf(v.x * g_scale[j]     + g_shift[j],     0.f);
    o.y = fmaxf(v.y * g_scale[j + 1] + g_shift[j + 1], 0.f);
    o.z = fmaxf(v.z * g_scale[j + 2] + g_shift[j + 2], 0.f);
    o.w = fmaxf(v.w * g_scale[j + 3] + g_shift[j + 3], 0.f);
    ((float4*)g_h)[idx] = o;
}

// ---------------- global mean pool (batch is sorted) ----------------
__global__ void pool_k(const int* __restrict__ batch) {
    int j  = threadIdx.x;
    int r0 = blockIdx.x * 80;
    int cur = -1;
    float acc = 0.f;
    for (int r = 0; r < 80; r++) {
        int n = r0 + r;
        if (n >= Nn) break;
        int b = batch[n];
        if (b != cur) {
            if (cur >= 0) atomicAdd(&g_gsum[cur * Hh + j], acc);
            cur = b; acc = 0.f;
        }
        acc += g_h[(size_t)n * Hh + j];
    }
    if (cur >= 0) atomicAdd(&g_gsum[cur * Hh + j], acc);
}

__global__ void pooldiv_k() {
    int i = blockIdx.x * blockDim.x + threadIdx.x;
    if (i < GG * Hh) g_gsum[i] *= 1.f / fmaxf((float)g_gcnt[i >> 8], 1.f);
}

// ---------------- MLP head ----------------
// stage 0: g_gsum @ W + b -> g_m1 ;  stage 1: g_m1 @ W + b -> g_m2
__global__ void mlp_gemm_k(const float* __restrict__ W, const float* __restrict__ b, int stage) {
    const float* A   = (stage == 0) ? g_gsum : g_m1;
    float*       out = (stage == 0) ? g_m1   : g_m2;
    __shared__ float s[Hh];
    int tid = threadIdx.x;
    int g   = blockIdx.x;
    s[tid] = A[g * Hh + tid];
    __syncthreads();
    float sum = b[tid];
#pragma unroll 8
    for (int k = 0; k < Hh; k++) sum += s[k] * W[k * Hh + tid];
    out[g * Hh + tid] = sum;
}

// stage 0: BN+ReLU on g_m1 ; stage 1: BN on g_m2
__global__ void bn_small_k(const float* __restrict__ gamma, const float* __restrict__ beta, int stage) {
    float* data = (stage == 0) ? g_m1 : g_m2;
    int relu = (stage == 0);
    int j = threadIdx.x;
    float s = 0.f, q = 0.f;
    for (int g = 0; g < GG; g++) { float v = data[g * Hh + j]; s += v; q += v * v; }
    float m   = s * (1.f / GG);
    float var = q * (1.f / GG) - m * m;
    float rs  = rsqrtf(var + EPSF);
    float sc  = gamma[j] * rs;
    float sh  = beta[j] - m * sc;
    for (int g = 0; g < GG; g++) {
        float v = data[g * Hh + j] * sc + sh;
        if (relu) v = fmaxf(v, 0.f);
        data[g * Hh + j] = v;
    }
}

__global__ void final_k(const float* __restrict__ W3, const float* __restrict__ b3,
                        float* __restrict__ out) {
    __shared__ float s[Hh];
    int tid = threadIdx.x;
    int g   = blockIdx.x;
    s[tid] = g_m2[g * Hh + tid];
    __syncthreads();
    if (tid < CC) {
        float sum = b3[tid];
        for (int k = 0; k < Hh; k++) sum += s[k] * W3[k * CC + tid];
        out[g * CC + tid] = sum;
    }
}

// ---------------- launch ----------------
extern "C" void kernel_launch(void* const* d_in, const int* in_sizes, int n_in,
                              void* d_out, int out_size) {
    const float* x     = (const float*)d_in[0];
    const int*   ei    = (const int*)  d_in[1];
    const int*   batch = (const int*)  d_in[2];
    const float* encW  = (const float*)d_in[3];
    const float* encB  = (const float*)d_in[4];
    const float* convW = (const float*)d_in[5];
    const float* convB = (const float*)d_in[6];
    const float* bnG   = (const float*)d_in[7];
    const float* bnB   = (const float*)d_in[8];
    const float* fcW1  = (const float*)d_in[9];
    const float* fcB1  = (const float*)d_in[10];
    const float* fcG1  = (const float*)d_in[11];
    const float* fcBe1 = (const float*)d_in[12];
    const float* fcW2  = (const float*)d_in[13];
    const float* fcB2  = (const float*)d_in[14];
    const float* fcG2  = (const float*)d_in[15];
    const float* fcBe2 = (const float*)d_in[16];
    const float* fcW3  = (const float*)d_in[17];
    const float* fcB3  = (const float*)d_in[18];
    const int* srcp = ei;
    const int* dstp = ei + Ee;
    float* out = (float*)d_out;

    // setup + CSR build (per call, deterministic)
    zero_k  <<<(GG * Hh + 255) / 256, 256>>>();
    degree_k<<<(Ee + 255) / 256, 256>>>(dstp, batch);
    dinv_k  <<<(Nn + 255) / 256, 256>>>();
    scan_k  <<<1, 1024>>>();
    place_k <<<(Ee + 255) / 256, 256>>>(srcp, dstp);

    // encoder
    dim3 gg(Hh / 64, (Nn + 63) / 64);
    gemm_enc_k<<<gg, 256>>>(x, encW, encB);

    // conv layers
    int aggBlocks   = (Nn * 32 + 255) / 256;
    int bnBlocks    = (Nn * Hh / 4 + 255) / 256;
    for (int l = 0; l < LL; l++) {
        gemm_conv_k<<<gg, 256>>>(convW + (size_t)l * Hh * Hh);
        agg_k   <<<aggBlocks, 256>>>(convB + l * Hh);
        stats_k <<<250, 256>>>();
        bnprep_k<<<1, 256>>>(bnG + l * Hh, bnB + l * Hh, 1.f / (float)Nn);
        bnrelu_k<<<bnBlocks, 256>>>();
    }

    // pool
    pool_k   <<<250, 256>>>(batch);
    pooldiv_k<<<(GG * Hh + 255) / 256, 256>>>();

    // MLP head
    mlp_gemm_k<<<GG, 256>>>(fcW1, fcB1, 0);
    bn_small_k<<<1, 256>>>(fcG1, fcBe1, 0);
    mlp_gemm_k<<<GG, 256>>>(fcW2, fcB2, 1);
    bn_small_k<<<1, 256>>>(fcG2, fcBe2, 1);
    final_k   <<<GG, 256>>>(fcW3, fcB3, out);
}

// round 3
// speedup vs baseline: 1.0233x; 1.0233x over previous
#include <cuda_runtime.h>
#include <cstdint>

#define Nn   20000
#define Ee   320000
#define XDIM 128
#define Hh   256
#define LL   4
#define GG   128
#define CC   10
#define EPSF 1e-5f

// ---------------- scratch (static device allocations) ----------------
__device__ float g_h [Nn * Hh];
__device__ float g_t [Nn * Hh];
__device__ float g_t2[Nn * Hh];
__device__ float g_dinv[Nn];
__device__ int   g_deg[Nn];
__device__ int   g_rowptr[Nn + 1];
__device__ int   g_cursor[Nn];
__device__ int   g_csrc[Ee];
__device__ float g_cw[Ee];
__device__ float g_colsum[Hh];
__device__ float g_colsq[Hh];
__device__ float g_scale[Hh];
__device__ float g_shift[Hh];
__device__ float g_gsum[GG * Hh];
__device__ int   g_gcnt[GG];
__device__ float g_m1[GG * Hh];
__device__ float g_m2[GG * Hh];

// ---------------- setup kernels ----------------
__global__ void zero_k() {
    int i = blockIdx.x * blockDim.x + threadIdx.x;
    if (i < Nn)      g_deg[i]  = 0;
    if (i < GG * Hh) g_gsum[i] = 0.f;
    if (i < GG)      g_gcnt[i] = 0;
}

__global__ void degree_k(const int* __restrict__ dst, const int* __restrict__ batch) {
    int i = blockIdx.x * blockDim.x + threadIdx.x;
    if (i < Ee) atomicAdd(&g_deg[dst[i]], 1);
    if (i < Nn) atomicAdd(&g_gcnt[batch[i]], 1);
}

__global__ void dinv_k() {
    int i = blockIdx.x * blockDim.x + threadIdx.x;
    if (i < Nn) g_dinv[i] = rsqrtf((float)g_deg[i] + 1.0f);
}

// single-block exclusive scan of g_deg -> g_rowptr (parallel: shfl warp scan)
__global__ void scan_k() {
    __shared__ int wsum[32];
    const int CH = 20;
    int tid = threadIdx.x, lane = tid & 31, wid = tid >> 5;
    int base = tid * CH;
    int loc[CH];
    int s = 0;
#pragma unroll
    for (int c = 0; c < CH; c++) {
        int idx = base + c;
        int v   = (idx < Nn) ? g_deg[idx] : 0;
        loc[c]  = s;
        s += v;
    }
    int inc = s;
#pragma unroll
    for (int o = 1; o < 32; o <<= 1) {
        int t = __shfl_up_sync(0xffffffffu, inc, o);
        if (lane >= o) inc += t;
    }
    if (lane == 31) wsum[wid] = inc;
    __syncthreads();
    if (wid == 0) {
        int v = wsum[lane];
        int iv = v;
#pragma unroll
        for (int o = 1; o < 32; o <<= 1) {
            int t = __shfl_up_sync(0xffffffffu, iv, o);
            if (lane >= o) iv += t;
        }
        wsum[lane] = iv - v;  // exclusive
    }
    __syncthreads();
    int off = wsum[wid] + (inc - s);
#pragma unroll
    for (int c = 0; c < CH; c++) {
        int idx = base + c;
        if (idx <= Nn) {
            int p = off + loc[c];
            g_rowptr[idx] = p;
            if (idx < Nn) g_cursor[idx] = p;
        }
    }
}

__global__ void place_k(const int* __restrict__ src, const int* __restrict__ dst) {
    int i = blockIdx.x * blockDim.x + threadIdx.x;
    if (i >= Ee) return;
    int s = src[i], d = dst[i];
    int pos = atomicAdd(&g_cursor[d], 1);
    g_csrc[pos] = s;
    g_cw[pos]   = g_dinv[s] * g_dinv[d];
}

// ---------------- TF32 tensor-core GEMM (3xTF32 split for fp32 accuracy) ----------------
#define BM 128
#define BN 64
#define BK 16
#define APAD 8
#define BPAD 8

__device__ __forceinline__ void mma_tf32(float4& d,
    uint32_t a0, uint32_t a1, uint32_t a2, uint32_t a3, uint32_t b0, uint32_t b1)
{
    asm volatile(
        "mma.sync.aligned.m16n8k8.row.col.f32.tf32.tf32.f32 "
        "{%0,%1,%2,%3}, {%4,%5,%6,%7}, {%8,%9}, {%0,%1,%2,%3};\n"
        : "+f"(d.x), "+f"(d.y), "+f"(d.z), "+f"(d.w)
        : "r"(a0), "r"(a1), "r"(a2), "r"(a3), "r"(b0), "r"(b1));
}

__device__ __forceinline__ void split_tf32(float x, uint32_t& hi, uint32_t& lo) {
    uint32_t h;
    asm("cvt.rna.tf32.f32 %0, %1;" : "=r"(h) : "f"(x));
    float r = x - __uint_as_float(h);
    uint32_t l;
    asm("cvt.rna.tf32.f32 %0, %1;" : "=r"(l) : "f"(r));
    hi = h; lo = l;
}

// C[M,256] = A[M,K] @ B[K,256] (+bias). K % 16 == 0.
__device__ __forceinline__ void gemm_mma_body(
    const float* __restrict__ A, const float* __restrict__ B,
    const float* __restrict__ bias, float* __restrict__ C, int M, int K)
{
    __shared__ uint32_t Ah[BK][BM + APAD], Al[BK][BM + APAD];
    __shared__ uint32_t Bh[BK][BN + BPAD], Bl[BK][BN + BPAD];

    const int tid  = threadIdx.x;
    const int lane = tid & 31, wid = tid >> 5;
    const int warp_m = wid & 3;        // 0..3 -> 32-row slab
    const int warp_n = wid >> 2;       // 0..1 -> 32-col slab
    const int rowBase = blockIdx.y * BM;
    const int colBase = blockIdx.x * BN;

    const int arow = tid >> 1;         // 0..127
    const int ak8  = (tid & 1) * 8;    // 0 or 8
    const int bkr  = tid >> 4;         // 0..15
    const int bnc  = (tid & 15) * 4;   // 0..60

    float4 acc[2][4];
#pragma unroll
    for (int i = 0; i < 2; i++)
#pragma unroll
        for (int j = 0; j < 4; j++) acc[i][j] = make_float4(0.f, 0.f, 0.f, 0.f);

    const int q = lane >> 2;           // 0..7
    const int t = lane & 3;            // 0..3

    for (int k0 = 0; k0 < K; k0 += BK) {
        // --- load + split A tile (BM x BK) ---
        int gr = rowBase + arow;
        float4 v0 = make_float4(0.f, 0.f, 0.f, 0.f), v1 = v0;
        if (gr < M) {
            const float* ap = A + (size_t)gr * K + k0 + ak8;
            v0 = *(const float4*)ap;
            v1 = *(const float4*)(ap + 4);
        }
        split_tf32(v0.x, Ah[ak8 + 0][arow], Al[ak8 + 0][arow]);
        split_tf32(v0.y, Ah[ak8 + 1][arow], Al[ak8 + 1][arow]);
        split_tf32(v0.z, Ah[ak8 + 2][arow], Al[ak8 + 2][arow]);
        split_tf32(v0.w, Ah[ak8 + 3][arow], Al[ak8 + 3][arow]);
        split_tf32(v1.x, Ah[ak8 + 4][arow], Al[ak8 + 4][arow]);
        split_tf32(v1.y, Ah[ak8 + 5][arow], Al[ak8 + 5][arow]);
        split_tf32(v1.z, Ah[ak8 + 6][arow], Al[ak8 + 6][arow]);
        split_tf32(v1.w, Ah[ak8 + 7][arow], Al[ak8 + 7][arow]);

        // --- load + split B tile (BK x BN) ---
        float4 w = *(const float4*)(B + (size_t)(k0 + bkr) * Hh + colBase + bnc);
        split_tf32(w.x, Bh[bkr][bnc + 0], Bl[bkr][bnc + 0]);
        split_tf32(w.y, Bh[bkr][bnc + 1], Bl[bkr][bnc + 1]);
        split_tf32(w.z, Bh[bkr][bnc + 2], Bl[bkr][bnc + 2]);
        split_tf32(w.w, Bh[bkr][bnc + 3], Bl[bkr][bnc + 3]);
        __syncthreads();

#pragma unroll
        for (int ks = 0; ks < 2; ks++) {
            const int kb = ks * 8 + t;
            uint32_t bhf[4][2], blf[4][2];
#pragma unroll
            for (int j = 0; j < 4; j++) {
                int nb = warp_n * 32 + j * 8 + q;
                bhf[j][0] = Bh[kb][nb];     bhf[j][1] = Bh[kb + 4][nb];
                blf[j][0] = Bl[kb][nb];     blf[j][1] = Bl[kb + 4][nb];
            }
#pragma unroll
            for (int i = 0; i < 2; i++) {
                int r0 = warp_m * 32 + i * 16 + q;
                uint32_t ah0 = Ah[kb][r0],     ah1 = Ah[kb][r0 + 8];
                uint32_t ah2 = Ah[kb + 4][r0], ah3 = Ah[kb + 4][r0 + 8];
                uint32_t al0 = Al[kb][r0],     al1 = Al[kb][r0 + 8];
                uint32_t al2 = Al[kb + 4][r0], al3 = Al[kb + 4][r0 + 8];
#pragma unroll
                for (int j = 0; j < 4; j++) {
                    mma_tf32(acc[i][j], ah0, ah1, ah2, ah3, bhf[j][0], bhf[j][1]);
                    mma_tf32(acc[i][j], ah0, ah1, ah2, ah3, blf[j][0], blf[j][1]);
                    mma_tf32(acc[i][j], al0, al1, al2, al3, bhf[j][0], bhf[j][1]);
                }
            }
        }
        __syncthreads();
    }

    // --- epilogue ---
#pragma unroll
    for (int i = 0; i < 2; i++) {
#pragma unroll
        for (int j = 0; j < 4; j++) {
            int r0 = rowBase + warp_m * 32 + i * 16 + q;
            int c  = colBase + warp_n * 32 + j * 8 + t * 2;
            float bx = 0.f, by = 0.f;
            if (bias) { bx = bias[c]; by = bias[c + 1]; }
            if (r0 < M) {
                C[(size_t)r0 * Hh + c]     = acc[i][j].x + bx;
                C[(size_t)r0 * Hh + c + 1] = acc[i][j].y + by;
            }
            if (r0 + 8 < M) {
                C[(size_t)(r0 + 8) * Hh + c]     = acc[i][j].z + bx;
                C[(size_t)(r0 + 8) * Hh + c + 1] = acc[i][j].w + by;
            }
        }
    }
}

__global__ __launch_bounds__(256) void gemm_enc_k(
    const float* __restrict__ x, const float* __restrict__ encW, const float* __restrict__ encB)
{
    gemm_mma_body(x, encW, encB, g_h, Nn, XDIM);
}

__global__ __launch_bounds__(256) void gemm_conv_k(const float* __restrict__ W)
{
    gemm_mma_body(g_h, W, nullptr, g_t, Nn, Hh);
}

// ---------------- aggregate (warp per node, CSR gather) + self loop + bias ----------------
__global__ __launch_bounds__(256) void agg_k(const float* __restrict__ convBi) {
    int gtid = blockIdx.x * blockDim.x + threadIdx.x;
    if (gtid < Hh) { g_colsum[gtid] = 0.f; g_colsq[gtid] = 0.f; }  // zero stats for this layer
    int w = gtid >> 5, lane = gtid & 31;
    if (w >= Nn) return;
    int beg = g_rowptr[w], end = g_rowptr[w + 1];
    float4 a0 = make_float4(0.f, 0.f, 0.f, 0.f), a1 = a0;
    const float4* T = (const float4*)g_t;
    for (int e = beg; e < end; e++) {
        int   s  = g_csrc[e];
        float wt = g_cw[e];
        float4 v0 = T[s * 64 + lane];
        float4 v1 = T[s * 64 + lane + 32];
        a0.x += v0.x * wt; a0.y += v0.y * wt; a0.z += v0.z * wt; a0.w += v0.w * wt;
        a1.x += v1.x * wt; a1.y += v1.y * wt; a1.z += v1.z * wt; a1.w += v1.w * wt;
    }
    float sn = g_dinv[w]; sn *= sn;
    float4 t0 = T[w * 64 + lane], t1 = T[w * 64 + lane + 32];
    const float4* B4 = (const float4*)convBi;
    float4 b0 = B4[lane], b1 = B4[lane + 32];
    a0.x += t0.x * sn + b0.x; a0.y += t0.y * sn + b0.y;
    a0.z += t0.z * sn + b0.z; a0.w += t0.w * sn + b0.w;
    a1.x += t1.x * sn + b1.x; a1.y += t1.y * sn + b1.y;
    a1.z += t1.z * sn + b1.z; a1.w += t1.w * sn + b1.w;
    ((float4*)g_t2)[w * 64 + lane]      = a0;
    ((float4*)g_t2)[w * 64 + lane + 32] = a1;
}

// ---------------- column stats over g_t2 ----------------
__global__ void stats_k() {
    int j  = threadIdx.x;
    int r0 = blockIdx.x * 80;
    float s = 0.f, q = 0.f;
    for (int r = 0; r < 80; r++) {
        int n = r0 + r;
        if (n >= Nn) break;
        float v = g_t2[(size_t)n * Hh + j];
        s += v; q += v * v;
    }
    atomicAdd(&g_colsum[j], s);
    atomicAdd(&g_colsq[j], q);
}

__global__ void bnprep_k(const float* __restrict__ gamma, const float* __restrict__ beta, float invN) {
    int j = threadIdx.x;
    float m  = g_colsum[j] * invN;
    float v  = g_colsq[j] * invN - m * m;
    float rs = rsqrtf(v + EPSF);
    float sc = gamma[j] * rs;
    g_scale[j] = sc;
    g_shift[j] = beta[j] - m * sc;
}

__global__ void bnrelu_k() {
    int idx = blockIdx.x * blockDim.x + threadIdx.x;
    if (idx >= Nn * Hh / 4) return;
    int j = (idx & (Hh / 4 - 1)) * 4;
    float4 v = ((const float4*)g_t2)[idx];
    float4 o;
    o.x = fmaxf(v.x * g_scale[j]     + g_shift[j],     0.f);
    o.y = fmaxf(v.y * g_scale[j + 1] + g_shift[j + 1], 0.f);
    o.z = fmaxf(v.z * g_scale[j + 2] + g_shift[j + 2], 0.f);
    o.w = fmaxf(v.w * g_scale[j + 3] + g_shift[j + 3], 0.f);
    ((float4*)g_h)[idx] = o;
}

// ---------------- global mean pool (batch is sorted) ----------------
__global__ void pool_k(const int* __restrict__ batch) {
    int j  = threadIdx.x;
    int r0 = blockIdx.x * 80;
    int cur = -1;
    float acc = 0.f;
    for (int r = 0; r < 80; r++) {
        int n = r0 + r;
        if (n >= Nn) break;
        int b = batch[n];
        if (b != cur) {
            if (cur >= 0) atomicAdd(&g_gsum[cur * Hh + j], acc);
            cur = b; acc = 0.f;
        }
        acc += g_h[(size_t)n * Hh + j];
    }
    if (cur >= 0) atomicAdd(&g_gsum[cur * Hh + j], acc);
}

__global__ void pooldiv_k() {
    int i = blockIdx.x * blockDim.x + threadIdx.x;
    if (i < GG * Hh) g_gsum[i] *= 1.f / fmaxf((float)g_gcnt[i >> 8], 1.f);
}

// ---------------- MLP head ----------------
__global__ void mlp_gemm_k(const float* __restrict__ W, const float* __restrict__ b, int stage) {
    const float* A   = (stage == 0) ? g_gsum : g_m1;
    float*       out = (stage == 0) ? g_m1   : g_m2;
    __shared__ float s[Hh];
    int tid = threadIdx.x;
    int g   = blockIdx.x;
    s[tid] = A[g * Hh + tid];
    __syncthreads();
    float sum = b[tid];
#pragma unroll 8
    for (int k = 0; k < Hh; k++) sum += s[k] * W[k * Hh + tid];
    out[g * Hh + tid] = sum;
}

__global__ void bn_small_k(const float* __restrict__ gamma, const float* __restrict__ beta, int stage) {
    float* data = (stage == 0) ? g_m1 : g_m2;
    int relu = (stage == 0);
    int j = threadIdx.x;
    float s = 0.f, q = 0.f;
    for (int g = 0; g < GG; g++) { float v = data[g * Hh + j]; s += v; q += v * v; }
    float m   = s * (1.f / GG);
    float var = q * (1.f / GG) - m * m;
    float rs  = rsqrtf(var + EPSF);
    float sc  = gamma[j] * rs;
    float sh  = beta[j] - m * sc;
    for (int g = 0; g < GG; g++) {
        float v = data[g * Hh + j] * sc + sh;
        if (relu) v = fmaxf(v, 0.f);
        data[g * Hh + j] = v;
    }
}

__global__ void final_k(const float* __restrict__ W3, const float* __restrict__ b3,
                        float* __restrict__ out) {
    __shared__ float s[Hh];
    int tid = threadIdx.x;
    int g   = blockIdx.x;
    s[tid] = g_m2[g * Hh + tid];
    __syncthreads();
    if (tid < CC) {
        float sum = b3[tid];
        for (int k = 0; k < Hh; k++) sum += s[k] * W3[k * CC + tid];
        out[g * CC + tid] = sum;
    }
}

// ---------------- launch ----------------
extern "C" void kernel_launch(void* const* d_in, const int* in_sizes, int n_in,
                              void* d_out, int out_size) {
    const float* x     = (const float*)d_in[0];
    const int*   ei    = (const int*)  d_in[1];
    const int*   batch = (const int*)  d_in[2];
    const float* encW  = (const float*)d_in[3];
    const float* encB  = (const float*)d_in[4];
    const float* convW = (const float*)d_in[5];
    const float* convB = (const float*)d_in[6];
    const float* bnG   = (const float*)d_in[7];
    const float* bnB   = (const float*)d_in[8];
    const float* fcW1  = (const float*)d_in[9];
    const float* fcB1  = (const float*)d_in[10];
    const float* fcG1  = (const float*)d_in[11];
    const float* fcBe1 = (const float*)d_in[12];
    const float* fcW2  = (const float*)d_in[13];
    const float* fcB2  = (const float*)d_in[14];
    const float* fcG2  = (const float*)d_in[15];
    const float* fcBe2 = (const float*)d_in[16];
    const float* fcW3  = (const float*)d_in[17];
    const float* fcB3  = (const float*)d_in[18];
    const int* srcp = ei;
    const int* dstp = ei + Ee;
    float* out = (float*)d_out;

    // setup + CSR build (per call, deterministic)
    zero_k  <<<(GG * Hh + 255) / 256, 256>>>();
    degree_k<<<(Ee + 255) / 256, 256>>>(dstp, batch);
    dinv_k  <<<(Nn + 255) / 256, 256>>>();
    scan_k  <<<1, 1024>>>();
    place_k <<<(Ee + 255) / 256, 256>>>(srcp, dstp);

    // encoder
    dim3 gg(Hh / BN, (Nn + BM - 1) / BM);
    gemm_enc_k<<<gg, 256>>>(x, encW, encB);

    // conv layers
    int aggBlocks = (Nn * 32 + 255) / 256;
    int bnBlocks  = (Nn * Hh / 4 + 255) / 256;
    for (int l = 0; l < LL; l++) {
        gemm_conv_k<<<gg, 256>>>(convW + (size_t)l * Hh * Hh);
        agg_k   <<<aggBlocks, 256>>>(convB + l * Hh);
        stats_k <<<250, 256>>>();
        bnprep_k<<<1, 256>>>(bnG + l * Hh, bnB + l * Hh, 1.f / (float)Nn);
        bnrelu_k<<<bnBlocks, 256>>>();
    }

    // pool
    pool_k   <<<250, 256>>>(batch);
    pooldiv_k<<<(GG * Hh + 255) / 256, 256>>>();

    // MLP head
    mlp_gemm_k<<<GG, 256>>>(fcW1, fcB1, 0);
    bn_small_k<<<1, 256>>>(fcG1, fcBe1, 0);
    mlp_gemm_k<<<GG, 256>>>(fcW2, fcB2, 1);
    bn_small_k<<<1, 256>>>(fcG2, fcBe2, 1);
    final_k   <<<GG, 256>>>(fcW3, fcB3, out);
}